// round 1
// baseline (speedup 1.0000x reference)
#include <cuda_runtime.h>
#include <math.h>

// Problem constants
constexpr int N_  = 4;
constexpr int P_  = 2048;
constexpr int D_  = 512;
constexpr int H_  = 8;
constexpr int HD_ = 64;
constexpr int NH_ = N_ * H_;                       // 32
constexpr long long NPD_  = (long long)N_ * P_ * D_;        // 4194304 (out elems)
constexpr long long NHPP_ = (long long)N_ * H_ * P_ * P_;   // 134217728 (attention elems)

// Scratch (device globals; allocation-free per harness rules)
__device__ float g_q[NH_ * P_ * HD_];   // [nh][p][e]
__device__ float g_k[NH_ * P_ * HD_];
__device__ float g_v[NH_ * P_ * HD_];
__device__ float g_o[NH_ * P_ * HD_];   // attention@V, per-head layout
__device__ float g_m[NH_ * P_];         // row max
__device__ float g_l[NH_ * P_];         // 1/row sumexp
__device__ float g_attn[NHPP_];         // fallback if attention not in d_out

// ---------------------------------------------------------------------------
// K1: QKV projection. q[n,p,h,e] = sum_d x[n,p,h,d] * W[e,d]
// One block per (nh, 64-row p-tile). 256 threads, 4x4 micro-tile, 3 passes.
// ---------------------------------------------------------------------------
__global__ __launch_bounds__(256) void qkv_kernel(
    const float* __restrict__ xyz,
    const float* __restrict__ Wq,
    const float* __restrict__ Wk,
    const float* __restrict__ Wv)
{
    __shared__ float xs[64][65];   // [row][dd]
    __shared__ float Wt[64][68];   // [dd][e]

    int ptile = blockIdx.x;        // 0..31
    int nh    = blockIdx.y;        // 0..31
    int n = nh / H_, h = nh % H_;
    int p0 = ptile * 64;
    int tid = threadIdx.x;

    for (int i = tid; i < 64 * 64; i += 256) {
        int row = i >> 6, dd = i & 63;
        xs[row][dd] = xyz[(n * P_ + p0 + row) * D_ + h * HD_ + dd];
    }

    int tx = tid & 15, ty = tid >> 4;
    int r = ty * 4, c = tx * 4;

    const float* Ws[3] = {Wq, Wk, Wv};
    float* Gs[3] = {g_q, g_k, g_v};

    for (int m = 0; m < 3; ++m) {
        __syncthreads();
        const float* W = Ws[m];
        for (int i = tid; i < 64 * 64; i += 256) {
            int e = i >> 6, dd = i & 63;
            Wt[dd][e] = W[i];
        }
        __syncthreads();

        float acc[4][4] = {};
        #pragma unroll
        for (int dd = 0; dd < 64; ++dd) {
            float a0 = xs[r + 0][dd], a1 = xs[r + 1][dd];
            float a2 = xs[r + 2][dd], a3 = xs[r + 3][dd];
            float4 b = *(const float4*)&Wt[dd][c];
            acc[0][0] += a0 * b.x; acc[0][1] += a0 * b.y; acc[0][2] += a0 * b.z; acc[0][3] += a0 * b.w;
            acc[1][0] += a1 * b.x; acc[1][1] += a1 * b.y; acc[1][2] += a1 * b.z; acc[1][3] += a1 * b.w;
            acc[2][0] += a2 * b.x; acc[2][1] += a2 * b.y; acc[2][2] += a2 * b.z; acc[2][3] += a2 * b.w;
            acc[3][0] += a3 * b.x; acc[3][1] += a3 * b.y; acc[3][2] += a3 * b.z; acc[3][3] += a3 * b.w;
        }

        float* G = Gs[m] + (nh * P_ + p0) * HD_;
        #pragma unroll
        for (int i = 0; i < 4; ++i) {
            float4 o = make_float4(acc[i][0], acc[i][1], acc[i][2], acc[i][3]);
            *(float4*)&G[(r + i) * HD_ + c] = o;
        }
    }
}

// ---------------------------------------------------------------------------
// K2: S = scale * Q @ K^T per (n,h). 128x128 block tile, 8x8 per-thread tile.
// Dynamic smem: Qt[64][132] + Kt[64][132] = 67.6 KB.
// ---------------------------------------------------------------------------
__global__ __launch_bounds__(256) void scores_kernel(float* __restrict__ attn)
{
    extern __shared__ float sm[];
    float (*Qt)[132] = (float (*)[132])sm;
    float (*Kt)[132] = (float (*)[132])(sm + 64 * 132);

    int kt = blockIdx.x, qt = blockIdx.y, nh = blockIdx.z;
    int q0 = qt * 128, k0 = kt * 128;
    int tid = threadIdx.x;
    const float scale = rsqrtf((float)D_);   // reference divides by sqrt(D=512)

    const float* Q = g_q + nh * P_ * HD_;
    const float* K = g_k + nh * P_ * HD_;

    for (int i = tid; i < 128 * 64; i += 256) {
        int row = i >> 6, dd = i & 63;
        Qt[dd][row] = Q[(q0 + row) * HD_ + dd] * scale;
        Kt[dd][row] = K[(k0 + row) * HD_ + dd];
    }
    __syncthreads();

    int tx = tid & 15, ty = tid >> 4;
    int r = ty * 8, c = tx * 8;

    float acc[8][8] = {};
    #pragma unroll
    for (int dd = 0; dd < 64; ++dd) {
        float4 a0 = *(const float4*)&Qt[dd][r];
        float4 a1 = *(const float4*)&Qt[dd][r + 4];
        float4 b0 = *(const float4*)&Kt[dd][c];
        float4 b1 = *(const float4*)&Kt[dd][c + 4];
        float a[8] = {a0.x, a0.y, a0.z, a0.w, a1.x, a1.y, a1.z, a1.w};
        float b[8] = {b0.x, b0.y, b0.z, b0.w, b1.x, b1.y, b1.z, b1.w};
        #pragma unroll
        for (int i = 0; i < 8; ++i)
            #pragma unroll
            for (int j = 0; j < 8; ++j)
                acc[i][j] += a[i] * b[j];
    }

    float* Srow = attn + (long long)nh * P_ * P_;
    #pragma unroll
    for (int i = 0; i < 8; ++i) {
        float4 v0 = make_float4(acc[i][0], acc[i][1], acc[i][2], acc[i][3]);
        float4 v1 = make_float4(acc[i][4], acc[i][5], acc[i][6], acc[i][7]);
        long long base = (long long)(q0 + r + i) * P_ + k0 + c;
        *(float4*)&Srow[base]     = v0;
        *(float4*)&Srow[base + 4] = v1;
    }
}

// ---------------------------------------------------------------------------
// K3: per-row max and 1/sumexp. One warp per row (2048 elems, 64/lane).
// ---------------------------------------------------------------------------
__global__ __launch_bounds__(256) void rowstats_kernel(const float* __restrict__ attn)
{
    int warp = (blockIdx.x * blockDim.x + threadIdx.x) >> 5;
    int lane = threadIdx.x & 31;
    if (warp >= NH_ * P_) return;

    const float* row = attn + (long long)warp * P_;
    float vals[64];
    float mx = -INFINITY;
    #pragma unroll
    for (int i = 0; i < 64; ++i) {
        vals[i] = row[i * 32 + lane];
        mx = fmaxf(mx, vals[i]);
    }
    #pragma unroll
    for (int o = 16; o; o >>= 1) mx = fmaxf(mx, __shfl_xor_sync(0xFFFFFFFFu, mx, o));

    float s = 0.f;
    #pragma unroll
    for (int i = 0; i < 64; ++i) s += __expf(vals[i] - mx);
    #pragma unroll
    for (int o = 16; o; o >>= 1) s += __shfl_xor_sync(0xFFFFFFFFu, s, o);

    if (lane == 0) {
        g_m[warp] = mx;
        g_l[warp] = 1.f / s;
    }
}

// ---------------------------------------------------------------------------
// K4: probs = softmax(S) written in place; O = probs @ V fused in same pass.
// Block: 128 q-rows x 64 e-cols; k-chunks of 32; 8x4 per-thread tile.
// ---------------------------------------------------------------------------
__global__ __launch_bounds__(256) void pv_kernel(float* __restrict__ attn)
{
    __shared__ float St[32][132];
    __shared__ float Vs[32][68];
    __shared__ float rm[128], rl[128];

    int qt = blockIdx.x, nh = blockIdx.y;
    int q0 = qt * 128;
    int tid = threadIdx.x;

    if (tid < 128) {
        rm[tid] = g_m[nh * P_ + q0 + tid];
        rl[tid] = g_l[nh * P_ + q0 + tid];
    }
    __syncthreads();

    const float* V = g_v + nh * P_ * HD_;
    float* S = attn + (long long)nh * P_ * P_;

    int tx = tid & 15, ty = tid >> 4;
    int r = ty * 8, c = tx * 4;
    float acc[8][4] = {};

    for (int kb = 0; kb < P_; kb += 32) {
        #pragma unroll 4
        for (int i = tid; i < 128 * 32; i += 256) {
            int row = i >> 5, kk = i & 31;
            long long gidx = (long long)(q0 + row) * P_ + kb + kk;
            float p = __expf(S[gidx] - rm[row]) * rl[row];
            S[gidx] = p;            // write normalized attention probs
            St[kk][row] = p;
        }
        #pragma unroll 4
        for (int i = tid; i < 32 * 64; i += 256) {
            int kk = i >> 6, e = i & 63;
            Vs[kk][e] = V[(kb + kk) * HD_ + e];
        }
        __syncthreads();

        #pragma unroll
        for (int kk = 0; kk < 32; ++kk) {
            float4 a0 = *(const float4*)&St[kk][r];
            float4 a1 = *(const float4*)&St[kk][r + 4];
            float4 b  = *(const float4*)&Vs[kk][c];
            float a[8] = {a0.x, a0.y, a0.z, a0.w, a1.x, a1.y, a1.z, a1.w};
            #pragma unroll
            for (int i = 0; i < 8; ++i) {
                acc[i][0] += a[i] * b.x;
                acc[i][1] += a[i] * b.y;
                acc[i][2] += a[i] * b.z;
                acc[i][3] += a[i] * b.w;
            }
        }
        __syncthreads();
    }

    float* O = g_o + (nh * P_ + q0) * HD_;
    #pragma unroll
    for (int i = 0; i < 8; ++i) {
        float4 o = make_float4(acc[i][0], acc[i][1], acc[i][2], acc[i][3]);
        *(float4*)&O[(r + i) * HD_ + c] = o;
    }
}

// ---------------------------------------------------------------------------
// K5: final = O_flat @ Wo^T + bo.  O_flat[n,p,h*64+hd] = g_o[nh][p][hd].
// 64x64 block tile, 4x4 per-thread tile, k-chunks of 64 (one head each).
// ---------------------------------------------------------------------------
__global__ __launch_bounds__(256) void outproj_kernel(
    const float* __restrict__ Wo,
    const float* __restrict__ bo,
    float* __restrict__ out)
{
    __shared__ float At[64][68];
    __shared__ float Bt[64][68];

    int ct = blockIdx.x;   // 8 col tiles
    int rt = blockIdx.y;   // 128 row tiles
    int r0 = rt * 64, c0 = ct * 64;
    int tid = threadIdx.x;
    int tx = tid & 15, ty = tid >> 4;
    int r = ty * 4, c = tx * 4;

    float acc[4][4] = {};

    for (int kb = 0; kb < D_; kb += 64) {
        int h = kb >> 6;
        for (int i = tid; i < 64 * 64; i += 256) {
            int row = i >> 6, kk = i & 63;
            int grow = r0 + row;
            int n = grow >> 11;         // / 2048
            int p = grow & 2047;
            At[kk][row] = g_o[((n * H_ + h) * P_ + p) * HD_ + kk];
        }
        for (int i = tid; i < 64 * 64; i += 256) {
            int e = i >> 6, kk = i & 63;
            Bt[kk][e] = Wo[(c0 + e) * D_ + kb + kk];
        }
        __syncthreads();

        #pragma unroll
        for (int kk = 0; kk < 64; ++kk) {
            float4 a = *(const float4*)&At[kk][r];
            float4 b = *(const float4*)&Bt[kk][c];
            float av[4] = {a.x, a.y, a.z, a.w};
            #pragma unroll
            for (int i = 0; i < 4; ++i) {
                acc[i][0] += av[i] * b.x;
                acc[i][1] += av[i] * b.y;
                acc[i][2] += av[i] * b.z;
                acc[i][3] += av[i] * b.w;
            }
        }
        __syncthreads();
    }

    float4 bias = *(const float4*)&bo[c0 + c];
    #pragma unroll
    for (int i = 0; i < 4; ++i) {
        float4 o = make_float4(acc[i][0] + bias.x, acc[i][1] + bias.y,
                               acc[i][2] + bias.z, acc[i][3] + bias.w);
        *(float4*)&out[(r0 + r + i) * D_ + c0 + c] = o;
    }
}

// ---------------------------------------------------------------------------
extern "C" void kernel_launch(void* const* d_in, const int* in_sizes, int n_in,
                              void* d_out, int out_size)
{
    const float* xyz = (const float*)d_in[0];
    const float* Wq  = (const float*)d_in[1];
    const float* Wk  = (const float*)d_in[2];
    const float* Wv  = (const float*)d_in[3];
    const float* Wo  = (const float*)d_in[4];
    const float* bo  = (const float*)d_in[5];
    float* out = (float*)d_out;

    // Attention probs are the 2nd output; prefer writing them directly into
    // d_out (after `out`). Fallback to device scratch if d_out is smaller.
    float* attn;
    if ((long long)out_size >= NPD_ + NHPP_) {
        attn = out + NPD_;
    } else {
        void* p = nullptr;
        cudaGetSymbolAddress(&p, g_attn);
        attn = (float*)p;
    }

    // Opt-in to >48KB dynamic smem for the scores GEMM (idempotent, cheap).
    cudaFuncSetAttribute(scores_kernel,
                         cudaFuncAttributeMaxDynamicSharedMemorySize,
                         2 * 64 * 132 * (int)sizeof(float));

    // K1: QKV projection
    qkv_kernel<<<dim3(P_ / 64, NH_), 256>>>(xyz, Wq, Wk, Wv);

    // K2: S = scale * Q K^T
    scores_kernel<<<dim3(P_ / 128, P_ / 128, NH_), 256,
                    2 * 64 * 132 * sizeof(float)>>>(attn);

    // K3: row max / inv-sumexp
    rowstats_kernel<<<(NH_ * P_ * 32 + 255) / 256, 256>>>(attn);

    // K4: softmax in place + O = P V
    pv_kernel<<<dim3(P_ / 128, NH_), 256>>>(attn);

    // K5: out = O @ Wo^T + bo
    outproj_kernel<<<dim3(D_ / 64, (N_ * P_) / 64), 256>>>(Wo, bo, out);
}

// round 5
// speedup vs baseline: 1.6339x; 1.6339x over previous
#include <cuda_runtime.h>
#include <cuda_bf16.h>
#include <stdint.h>
#include <math.h>

// Problem constants
constexpr int N_  = 4;
constexpr int P_  = 2048;
constexpr int D_  = 512;
constexpr int H_  = 8;
constexpr int HD_ = 64;
constexpr int NH_ = N_ * H_;                              // 32
constexpr long long NPD_  = (long long)N_ * P_ * D_;      // 4194304
constexpr long long NHPP_ = (long long)N_ * H_ * P_ * P_; // 134217728
constexpr float SCALE_ = 0.044194173824159216f;           // 1/sqrt(512)

// ---------------------------------------------------------------------------
// Scratch (device globals; allocation-free per harness rules)
// ---------------------------------------------------------------------------
__device__ __align__(16) __nv_bfloat16 g_qh[NH_ * P_ * HD_];  // scaled Q hi
__device__ __align__(16) __nv_bfloat16 g_ql[NH_ * P_ * HD_];  // scaled Q lo
__device__ __align__(16) __nv_bfloat16 g_kh[NH_ * P_ * HD_];
__device__ __align__(16) __nv_bfloat16 g_kl[NH_ * P_ * HD_];
__device__ __align__(16) __nv_bfloat16 g_vth[NH_ * HD_ * P_]; // V^T hi [nh][e][p]
__device__ __align__(16) __nv_bfloat16 g_vtl[NH_ * HD_ * P_]; // V^T lo
__device__ float g_o[NH_ * P_ * HD_];     // attention@V  [nh][p][e]
__device__ float g_pm[NH_ * 16 * P_];     // per-ktile row max partial
__device__ float g_ps[NH_ * 16 * P_];     // per-ktile row sumexp partial
__device__ float g_attn[NHPP_];           // fallback if attention not in d_out

// ---------------------------------------------------------------------------
// Helpers
// ---------------------------------------------------------------------------
__device__ __forceinline__ uint32_t smem_u32(const void* p) {
    uint32_t a;
    asm("{ .reg .u64 t; cvta.to.shared.u64 t, %1; cvt.u32.u64 %0, t; }"
        : "=r"(a) : "l"(p));
    return a;
}

__device__ __forceinline__ void ldsm4(uint32_t* r, uint32_t a) {
    asm volatile("ldmatrix.sync.aligned.m8n8.x4.shared.b16 {%0,%1,%2,%3}, [%4];"
                 : "=r"(r[0]), "=r"(r[1]), "=r"(r[2]), "=r"(r[3]) : "r"(a));
}

__device__ __forceinline__ void mma16816(float* d, const uint32_t* a,
                                         uint32_t b0, uint32_t b1) {
    asm volatile("mma.sync.aligned.m16n8k16.row.col.f32.bf16.bf16.f32 "
                 "{%0,%1,%2,%3},{%4,%5,%6,%7},{%8,%9},{%0,%1,%2,%3};"
                 : "+f"(d[0]), "+f"(d[1]), "+f"(d[2]), "+f"(d[3])
                 : "r"(a[0]), "r"(a[1]), "r"(a[2]), "r"(a[3]), "r"(b0), "r"(b1));
}

// Fast exp on the FFMA pipe (valid for x <= 0; ~1e-7 rel err). Avoids MUFU.
__device__ __forceinline__ float fexp(float x) {
    float t = x * 1.4426950408889634f;        // log2(e)
    t = fmaxf(t, -120.f);
    float z = t + 12582912.f;                  // 1.5*2^23 magic round
    int   n = __float_as_int(z) - 0x4B400000;  // round(t), signed
    float f = t - (z - 12582912.f);            // f in [-0.5, 0.5]
    float r = 1.5403530393381609e-4f;          // 2^f Taylor deg-6 (in ln2)
    r = fmaf(r, f, 1.3333558146428443e-3f);
    r = fmaf(r, f, 9.6181291076284772e-3f);
    r = fmaf(r, f, 5.5504108664821580e-2f);
    r = fmaf(r, f, 2.4022650695910072e-1f);
    r = fmaf(r, f, 6.9314718055994531e-1f);
    r = fmaf(r, f, 1.0f);
    return __int_as_float(__float_as_int(r) + (n << 23));
}

__device__ __forceinline__ unsigned short bfu(__nv_bfloat16 b) {
    return __bfloat16_as_ushort(b);
}

// ---------------------------------------------------------------------------
// K1: QKV projection (fp32 FFMA) -> bf16 hi/lo outputs.
//   Q pre-scaled by 1/sqrt(512). V stored transposed [nh][e][p].
// ---------------------------------------------------------------------------
__global__ __launch_bounds__(256) void qkv_kernel(
    const float* __restrict__ xyz,
    const float* __restrict__ Wq,
    const float* __restrict__ Wk,
    const float* __restrict__ Wv)
{
    __shared__ float xs[64][65];
    __shared__ float Wt[64][68];

    int ptile = blockIdx.x, nh = blockIdx.y;
    int n = nh / H_, h = nh % H_;
    int p0 = ptile * 64;
    int tid = threadIdx.x;

    for (int i = tid; i < 4096; i += 256) {
        int row = i >> 6, dd = i & 63;
        xs[row][dd] = xyz[(n * P_ + p0 + row) * D_ + h * HD_ + dd];
    }

    int tx = tid & 15, ty = tid >> 4;
    int r = ty * 4, c = tx * 4;
    const float* Ws[3] = {Wq, Wk, Wv};

    for (int m = 0; m < 3; ++m) {
        __syncthreads();
        const float* W = Ws[m];
        for (int i = tid; i < 4096; i += 256) {
            int e = i >> 6, dd = i & 63;
            Wt[dd][e] = W[i];
        }
        __syncthreads();

        float acc[4][4] = {};
        #pragma unroll
        for (int dd = 0; dd < 64; ++dd) {
            float a0 = xs[r + 0][dd], a1 = xs[r + 1][dd];
            float a2 = xs[r + 2][dd], a3 = xs[r + 3][dd];
            float4 b = *(const float4*)&Wt[dd][c];
            acc[0][0] += a0 * b.x; acc[0][1] += a0 * b.y; acc[0][2] += a0 * b.z; acc[0][3] += a0 * b.w;
            acc[1][0] += a1 * b.x; acc[1][1] += a1 * b.y; acc[1][2] += a1 * b.z; acc[1][3] += a1 * b.w;
            acc[2][0] += a2 * b.x; acc[2][1] += a2 * b.y; acc[2][2] += a2 * b.z; acc[2][3] += a2 * b.w;
            acc[3][0] += a3 * b.x; acc[3][1] += a3 * b.y; acc[3][2] += a3 * b.z; acc[3][3] += a3 * b.w;
        }

        if (m < 2) {
            float sc = (m == 0) ? SCALE_ : 1.0f;
            __nv_bfloat16* Ah = (m == 0) ? g_qh : g_kh;
            __nv_bfloat16* Al = (m == 0) ? g_ql : g_kl;
            #pragma unroll
            for (int i = 0; i < 4; ++i) {
                long long idx = ((long long)(nh * P_ + p0 + r + i)) * 64 + c;
                ushort4 uh, ul;
                float v0 = acc[i][0] * sc, v1 = acc[i][1] * sc;
                float v2 = acc[i][2] * sc, v3 = acc[i][3] * sc;
                __nv_bfloat16 h0 = __float2bfloat16(v0), h1 = __float2bfloat16(v1);
                __nv_bfloat16 h2 = __float2bfloat16(v2), h3 = __float2bfloat16(v3);
                uh = make_ushort4(bfu(h0), bfu(h1), bfu(h2), bfu(h3));
                ul = make_ushort4(bfu(__float2bfloat16(v0 - __bfloat162float(h0))),
                                  bfu(__float2bfloat16(v1 - __bfloat162float(h1))),
                                  bfu(__float2bfloat16(v2 - __bfloat162float(h2))),
                                  bfu(__float2bfloat16(v3 - __bfloat162float(h3))));
                *(ushort4*)&Ah[idx] = uh;
                *(ushort4*)&Al[idx] = ul;
            }
        } else {
            __syncthreads();
            #pragma unroll
            for (int i = 0; i < 4; ++i)
                #pragma unroll
                for (int j = 0; j < 4; ++j)
                    xs[c + j][r + i] = acc[i][j];
            __syncthreads();
            for (int i = tid; i < 4096; i += 256) {
                int e = i >> 6, pp = i & 63;
                float v = xs[e][pp];
                __nv_bfloat16 hb = __float2bfloat16(v);
                long long idx = (long long)(nh * 64 + e) * P_ + p0 + pp;
                g_vth[idx] = hb;
                g_vtl[idx] = __float2bfloat16(v - __bfloat162float(hb));
            }
        }
    }
}

// ---------------------------------------------------------------------------
// K2: S = (scaled Q) K^T via mma.sync bf16 hi/lo (3 passes).
//   Epilogue: writes u = exp(S - tile_rowmax) to attn (scratch for pv),
//   plus per-tile row max/sum partials.
// Block 256 thr, tile 128x128; warp (wm=wid>>1 rows 32, wn=wid&1 cols 64).
// smem: QH 0, QL 18432, KH 36864, KL 55296 (each 128 x 72 bf16, stride 144B);
//       after MMA reused as stage (128 x 132 f32 = 67584);
//       Mrow @68096, wmax @68608, wsum @69632. Total 73728.
// ---------------------------------------------------------------------------
constexpr int TSB = 144;  // bf16 tile row stride bytes (72 bf16)

__global__ __launch_bounds__(256) void scores_tc(float* __restrict__ attn)
{
    extern __shared__ char sm[];
    uint32_t sb = smem_u32(sm);
    int tid = threadIdx.x, lane = tid & 31, wid = tid >> 5;
    int kt = blockIdx.x, qt = blockIdx.y, nh = blockIdx.z;
    int q0 = qt * 128, k0 = kt * 128;

    const int QH = 0, QL = 18432, KH = 36864, KL = 55296;
    {
        const __nv_bfloat16* srcs[4] = {
            g_qh + (long long)(nh * P_ + q0) * 64,
            g_ql + (long long)(nh * P_ + q0) * 64,
            g_kh + (long long)(nh * P_ + k0) * 64,
            g_kl + (long long)(nh * P_ + k0) * 64};
        const int offs[4] = {QH, QL, KH, KL};
        #pragma unroll
        for (int t = 0; t < 4; ++t) {
            #pragma unroll
            for (int i = 0; i < 4; ++i) {
                int lin = i * 256 + tid;
                int row = lin >> 3, c8 = lin & 7;
                *(uint4*)(sm + offs[t] + row * TSB + c8 * 16) =
                    *(const uint4*)(srcs[t] + row * 64 + c8 * 8);
            }
        }
    }
    __syncthreads();

    int wm = wid >> 1, wn = wid & 1;
    float acc[2][8][4] = {};
    uint32_t aoff = (uint32_t)(wm * 32 + (lane & 15)) * TSB + ((lane & 16) ? 16u : 0u);
    uint32_t boff = (uint32_t)(wn * 64 + (lane & 7) + ((lane & 16) ? 8 : 0)) * TSB +
                    ((lane & 8) ? 16u : 0u);

    #pragma unroll
    for (int pass = 0; pass < 3; ++pass) {
        uint32_t Ab = sb + (pass == 2 ? QL : QH);
        uint32_t Bb = sb + (pass == 1 ? KL : KH);
        #pragma unroll
        for (int ks = 0; ks < 4; ++ks) {
            uint32_t af[2][4], bf2[4][4];
            ldsm4(af[0], Ab + aoff + ks * 32);
            ldsm4(af[1], Ab + aoff + 16 * TSB + ks * 32);
            #pragma unroll
            for (int np = 0; np < 4; ++np)
                ldsm4(bf2[np], Bb + boff + np * 16 * TSB + ks * 32);
            #pragma unroll
            for (int mi = 0; mi < 2; ++mi)
                #pragma unroll
                for (int ni = 0; ni < 8; ++ni)
                    mma16816(acc[mi][ni], af[mi],
                             bf2[ni >> 1][(ni & 1) * 2], bf2[ni >> 1][(ni & 1) * 2 + 1]);
        }
    }

    // ---- row stats + exp + stage ----
    float* stage = (float*)sm;                // stride 132 floats
    float* Mrow  = (float*)(sm + 68096);
    float* wmax  = (float*)(sm + 68608);
    float* wsum  = (float*)(sm + 69632);
    int g = lane >> 2, tg = lane & 3;

    #pragma unroll
    for (int mi = 0; mi < 2; ++mi)
        #pragma unroll
        for (int h = 0; h < 2; ++h) {
            float m = -1e30f;
            #pragma unroll
            for (int ni = 0; ni < 8; ++ni)
                m = fmaxf(m, fmaxf(acc[mi][ni][h * 2], acc[mi][ni][h * 2 + 1]));
            m = fmaxf(m, __shfl_xor_sync(0xFFFFFFFFu, m, 1));
            m = fmaxf(m, __shfl_xor_sync(0xFFFFFFFFu, m, 2));
            if (tg == 0) wmax[(wm * 32 + mi * 16 + h * 8 + g) * 2 + wn] = m;
        }
    __syncthreads();
    if (tid < 128) {
        float M = fmaxf(wmax[tid * 2], wmax[tid * 2 + 1]);
        Mrow[tid] = M;
        g_pm[(nh * 16 + kt) * P_ + q0 + tid] = M;
    }
    __syncthreads();
    #pragma unroll
    for (int mi = 0; mi < 2; ++mi)
        #pragma unroll
        for (int h = 0; h < 2; ++h) {
            int row = wm * 32 + mi * 16 + h * 8 + g;
            float M = Mrow[row];
            float s = 0.f;
            #pragma unroll
            for (int ni = 0; ni < 8; ++ni) {
                float u0 = fexp(acc[mi][ni][h * 2] - M);
                float u1 = fexp(acc[mi][ni][h * 2 + 1] - M);
                acc[mi][ni][h * 2] = u0;
                acc[mi][ni][h * 2 + 1] = u1;
                s += u0 + u1;
            }
            s += __shfl_xor_sync(0xFFFFFFFFu, s, 1);
            s += __shfl_xor_sync(0xFFFFFFFFu, s, 2);
            if (tg == 0) wsum[row * 2 + wn] = s;
        }
    __syncthreads();
    if (tid < 128)
        g_ps[(nh * 16 + kt) * P_ + q0 + tid] = wsum[tid * 2] + wsum[tid * 2 + 1];

    // stage u (operand smem dead; stats arrays live beyond 67584)
    #pragma unroll
    for (int mi = 0; mi < 2; ++mi)
        #pragma unroll
        for (int h = 0; h < 2; ++h) {
            int row = wm * 32 + mi * 16 + h * 8 + g;
            #pragma unroll
            for (int ni = 0; ni < 8; ++ni) {
                int col = wn * 64 + ni * 8 + tg * 2;
                *(float2*)&stage[row * 132 + col] =
                    make_float2(acc[mi][ni][h * 2], acc[mi][ni][h * 2 + 1]);
            }
        }
    __syncthreads();
    long long abase = ((long long)nh << 22) + (long long)q0 * 2048 + k0;
    #pragma unroll
    for (int i = 0; i < 16; ++i) {
        int lin = i * 256 + tid;
        int row = lin >> 5, c4 = lin & 31;
        *(float4*)&attn[abase + (long long)row * 2048 + c4 * 4] =
            *(float4*)&stage[row * 132 + c4 * 4];
    }
}

// ---------------------------------------------------------------------------
// K3: combine stats; probs = u * fac written in place (output);
//     O = P @ V via mma.sync over 16 k-tiles.
// Block 256 thr; warp = 16 q-rows x 64 e-cols.
// smem: PH 0, PL 34816 (128 x 136 bf16, stride 272B);
//       VH 69632, VL 87040 (64 x 136 bf16); FACS 104448 (128x16 f32).
//       Total 112640. Epilogue reuses PH as Ost (128 x 68 f32).
// ---------------------------------------------------------------------------
__global__ __launch_bounds__(256) void pv_tc(float* __restrict__ attn)
{
    extern __shared__ char sm[];
    uint32_t sb = smem_u32(sm);
    const int PH = 0, PL = 34816, VH = 69632, VL = 87040, FACS = 104448;
    int tid = threadIdx.x, lane = tid & 31, wid = tid >> 5;
    int qt = blockIdx.x, nh = blockIdx.y;
    int q0 = qt * 128;
    float* facs = (float*)(sm + FACS);

    if (tid < 128) {
        float pm[16];
        float M = -1e30f;
        #pragma unroll
        for (int t = 0; t < 16; ++t) {
            pm[t] = g_pm[(nh * 16 + t) * P_ + q0 + tid];
            M = fmaxf(M, pm[t]);
        }
        float L = 0.f, e[16];
        #pragma unroll
        for (int t = 0; t < 16; ++t) {
            e[t] = fexp(pm[t] - M);
            L += g_ps[(nh * 16 + t) * P_ + q0 + tid] * e[t];
        }
        float inv = 1.f / L;
        #pragma unroll
        for (int t = 0; t < 16; ++t) facs[tid * 16 + t] = e[t] * inv;
    }
    __syncthreads();

    const __nv_bfloat16* vh = g_vth + (long long)nh * 64 * P_;
    const __nv_bfloat16* vl = g_vtl + (long long)nh * 64 * P_;
    float* S = attn + ((long long)nh << 22) + (long long)q0 * 2048;

    float acc[8][4] = {};
    uint32_t aoff = (uint32_t)(wid * 16 + (lane & 15)) * 272 + ((lane & 16) ? 16u : 0u);
    uint32_t boff = (uint32_t)((lane & 7) + ((lane & 16) ? 8 : 0)) * 272 +
                    ((lane & 8) ? 16u : 0u);

    #pragma unroll 1
    for (int kb = 0; kb < 16; ++kb) {
        int k0 = kb * 128;
        #pragma unroll
        for (int i = 0; i < 4; ++i) {
            int lin = i * 256 + tid;
            int row = lin >> 4, c8 = lin & 15;
            uint32_t off = row * 272 + c8 * 16;
            *(uint4*)(sm + VH + off) = *(const uint4*)(vh + (long long)row * P_ + k0 + c8 * 8);
            *(uint4*)(sm + VL + off) = *(const uint4*)(vl + (long long)row * P_ + k0 + c8 * 8);
        }
        #pragma unroll 4
        for (int i = 0; i < 16; ++i) {
            int lin = i * 256 + tid;
            int row = lin >> 5, c4 = lin & 31;
            float4 sv = *(float4*)&S[(long long)row * 2048 + k0 + c4 * 4];
            float fac = facs[row * 16 + kb];
            float p0 = sv.x * fac, p1 = sv.y * fac, p2 = sv.z * fac, p3 = sv.w * fac;
            *(float4*)&S[(long long)row * 2048 + k0 + c4 * 4] = make_float4(p0, p1, p2, p3);
            __nv_bfloat16 h0 = __float2bfloat16(p0), h1 = __float2bfloat16(p1);
            __nv_bfloat16 h2 = __float2bfloat16(p2), h3 = __float2bfloat16(p3);
            ushort4 uh = make_ushort4(bfu(h0), bfu(h1), bfu(h2), bfu(h3));
            ushort4 ul = make_ushort4(bfu(__float2bfloat16(p0 - __bfloat162float(h0))),
                                      bfu(__float2bfloat16(p1 - __bfloat162float(h1))),
                                      bfu(__float2bfloat16(p2 - __bfloat162float(h2))),
                                      bfu(__float2bfloat16(p3 - __bfloat162float(h3))));
            uint32_t off = row * 272 + c4 * 8;
            *(ushort4*)(sm + PH + off) = uh;
            *(ushort4*)(sm + PL + off) = ul;
        }
        __syncthreads();

        #pragma unroll
        for (int pass = 0; pass < 3; ++pass) {
            uint32_t Ab = sb + (pass == 2 ? PL : PH);
            uint32_t Bb = sb + (pass == 1 ? VL : VH);
            #pragma unroll
            for (int ks = 0; ks < 8; ++ks) {
                uint32_t af[4], bf2[4][4];
                ldsm4(af, Ab + aoff + ks * 32);
                #pragma unroll
                for (int np = 0; np < 4; ++np)
                    ldsm4(bf2[np], Bb + boff + np * 16 * 272 + ks * 32);
                #pragma unroll
                for (int ni = 0; ni < 8; ++ni)
                    mma16816(acc[ni], af,
                             bf2[ni >> 1][(ni & 1) * 2], bf2[ni >> 1][(ni & 1) * 2 + 1]);
            }
        }
        __syncthreads();
    }

    // Epilogue: O (128 x 64 f32) -> staged -> coalesced store
    int g = lane >> 2, tg = lane & 3;
    float* Ost = (float*)sm;  // stride 68 floats
    #pragma unroll
    for (int h = 0; h < 2; ++h) {
        int row = wid * 16 + h * 8 + g;
        #pragma unroll
        for (int ni = 0; ni < 8; ++ni)
            *(float2*)&Ost[row * 68 + ni * 8 + tg * 2] =
                make_float2(acc[ni][h * 2], acc[ni][h * 2 + 1]);
    }
    __syncthreads();
    #pragma unroll
    for (int i = 0; i < 8; ++i) {
        int lin = i * 256 + tid;
        int row = lin >> 4, c4 = lin & 15;
        *(float4*)&g_o[((long long)(nh * P_ + q0 + row)) * 64 + c4 * 4] =
            *(float4*)&Ost[row * 68 + c4 * 4];
    }
}

// ---------------------------------------------------------------------------
// K4: final = O_flat @ Wo^T + bo (fp32).
// ---------------------------------------------------------------------------
__global__ __launch_bounds__(256) void outproj_kernel(
    const float* __restrict__ Wo,
    const float* __restrict__ bo,
    float* __restrict__ out)
{
    __shared__ float At[64][68];
    __shared__ float Bt[64][68];

    int ct = blockIdx.x, rt = blockIdx.y;
    int r0 = rt * 64, c0 = ct * 64;
    int tid = threadIdx.x;
    int tx = tid & 15, ty = tid >> 4;
    int r = ty * 4, c = tx * 4;

    float acc[4][4] = {};

    for (int kb = 0; kb < D_; kb += 64) {
        int h = kb >> 6;
        for (int i = tid; i < 4096; i += 256) {
            int row = i >> 6, kk = i & 63;
            int grow = r0 + row;
            int n = grow >> 11, p = grow & 2047;
            At[kk][row] = g_o[((n * H_ + h) * P_ + p) * HD_ + kk];
        }
        for (int i = tid; i < 4096; i += 256) {
            int e = i >> 6, kk = i & 63;
            Bt[kk][e] = Wo[(c0 + e) * D_ + kb + kk];
        }
        __syncthreads();

        #pragma unroll
        for (int kk = 0; kk < 64; ++kk) {
            float4 a = *(const float4*)&At[kk][r];
            float4 b = *(const float4*)&Bt[kk][c];
            float av[4] = {a.x, a.y, a.z, a.w};
            #pragma unroll
            for (int i = 0; i < 4; ++i) {
                acc[i][0] += av[i] * b.x;
                acc[i][1] += av[i] * b.y;
                acc[i][2] += av[i] * b.z;
                acc[i][3] += av[i] * b.w;
            }
        }
        __syncthreads();
    }

    float4 bias = *(const float4*)&bo[c0 + c];
    #pragma unroll
    for (int i = 0; i < 4; ++i) {
        float4 o = make_float4(acc[i][0] + bias.x, acc[i][1] + bias.y,
                               acc[i][2] + bias.z, acc[i][3] + bias.w);
        *(float4*)&out[(r0 + r + i) * D_ + c0 + c] = o;
    }
}

// ---------------------------------------------------------------------------
extern "C" void kernel_launch(void* const* d_in, const int* in_sizes, int n_in,
                              void* d_out, int out_size)
{
    const float* xyz = (const float*)d_in[0];
    const float* Wq  = (const float*)d_in[1];
    const float* Wk  = (const float*)d_in[2];
    const float* Wv  = (const float*)d_in[3];
    const float* Wo  = (const float*)d_in[4];
    const float* bo  = (const float*)d_in[5];
    float* out = (float*)d_out;

    float* attn;
    if ((long long)out_size >= NPD_ + NHPP_) {
        attn = out + NPD_;
    } else {
        void* p = nullptr;
        cudaGetSymbolAddress(&p, g_attn);
        attn = (float*)p;
    }

    cudaFuncSetAttribute(scores_tc, cudaFuncAttributeMaxDynamicSharedMemorySize, 73728);
    cudaFuncSetAttribute(pv_tc,     cudaFuncAttributeMaxDynamicSharedMemorySize, 112640);

    qkv_kernel<<<dim3(P_ / 64, NH_), 256>>>(xyz, Wq, Wk, Wv);
    scores_tc<<<dim3(16, 16, NH_), 256, 73728>>>(attn);
    pv_tc<<<dim3(16, NH_), 256, 112640>>>(attn);
    outproj_kernel<<<dim3(D_ / 64, (N_ * P_) / 64), 256>>>(Wo, bo, out);
}

// round 7
// speedup vs baseline: 2.7373x; 1.6753x over previous
#include <cuda_runtime.h>
#include <cuda_bf16.h>
#include <stdint.h>
#include <math.h>

// Problem constants
constexpr int N_  = 4;
constexpr int P_  = 2048;
constexpr int D_  = 512;
constexpr int H_  = 8;
constexpr int HD_ = 64;
constexpr int NH_ = N_ * H_;                              // 32
constexpr long long NPD_  = (long long)N_ * P_ * D_;      // 4194304
constexpr long long NHPP_ = (long long)N_ * H_ * P_ * P_; // 134217728
constexpr float SCALE_ = 0.044194173824159216f;           // 1/sqrt(512)

// ---------------------------------------------------------------------------
// Scratch (device globals; allocation-free per harness rules)
// ---------------------------------------------------------------------------
__device__ __align__(16) __nv_bfloat16 g_qh[NH_ * P_ * HD_];
__device__ __align__(16) __nv_bfloat16 g_ql[NH_ * P_ * HD_];
__device__ __align__(16) __nv_bfloat16 g_kh[NH_ * P_ * HD_];
__device__ __align__(16) __nv_bfloat16 g_kl[NH_ * P_ * HD_];
__device__ __align__(16) __nv_bfloat16 g_vth[NH_ * HD_ * P_]; // V^T [nh][e][p]
__device__ __align__(16) __nv_bfloat16 g_vtl[NH_ * HD_ * P_];
__device__ __align__(16) __nv_bfloat16 g_uh[NHPP_];  // u = exp(S - m_tile) hi
__device__ __align__(16) __nv_bfloat16 g_ul[NHPP_];  // u lo
__device__ __align__(16) __nv_bfloat16 g_oh[NPD_];   // O flat [n][p][512] hi
__device__ __align__(16) __nv_bfloat16 g_ol[NPD_];
__device__ __align__(16) __nv_bfloat16 g_woh[D_ * D_];
__device__ __align__(16) __nv_bfloat16 g_wol[D_ * D_];
__device__ float g_pm[NH_ * 16 * P_];     // per-ktile row max partial
__device__ float g_ps[NH_ * 16 * P_];     // per-ktile row sumexp partial
__device__ float g_attn[NHPP_];           // fallback if attention not in d_out

// ---------------------------------------------------------------------------
// Helpers
// ---------------------------------------------------------------------------
__device__ __forceinline__ uint32_t smem_u32(const void* p) {
    uint32_t a;
    asm("{ .reg .u64 t; cvta.to.shared.u64 t, %1; cvt.u32.u64 %0, t; }"
        : "=r"(a) : "l"(p));
    return a;
}

__device__ __forceinline__ void ldsm4(uint32_t* r, uint32_t a) {
    asm volatile("ldmatrix.sync.aligned.m8n8.x4.shared.b16 {%0,%1,%2,%3}, [%4];"
                 : "=r"(r[0]), "=r"(r[1]), "=r"(r[2]), "=r"(r[3]) : "r"(a));
}

__device__ __forceinline__ void mma16816(float* d, const uint32_t* a,
                                         uint32_t b0, uint32_t b1) {
    asm volatile("mma.sync.aligned.m16n8k16.row.col.f32.bf16.bf16.f32 "
                 "{%0,%1,%2,%3},{%4,%5,%6,%7},{%8,%9},{%0,%1,%2,%3};"
                 : "+f"(d[0]), "+f"(d[1]), "+f"(d[2]), "+f"(d[3])
                 : "r"(a[0]), "r"(a[1]), "r"(a[2]), "r"(a[3]), "r"(b0), "r"(b1));
}

__device__ __forceinline__ void cpa16(uint32_t d, const void* s) {
    asm volatile("cp.async.cg.shared.global [%0], [%1], 16;" :: "r"(d), "l"(s));
}
#define CP_COMMIT() asm volatile("cp.async.commit_group;" ::: "memory")
#define CP_WAIT1()  asm volatile("cp.async.wait_group 1;" ::: "memory")
#define CP_WAIT0()  asm volatile("cp.async.wait_group 0;" ::: "memory")

// Fast exp on the FFMA pipe (valid for x <= 0; ~1e-7 rel err). Avoids MUFU.
__device__ __forceinline__ float fexp(float x) {
    float t = x * 1.4426950408889634f;
    t = fmaxf(t, -120.f);
    float z = t + 12582912.f;
    int   n = __float_as_int(z) - 0x4B400000;
    float f = t - (z - 12582912.f);
    float r = 1.5403530393381609e-4f;
    r = fmaf(r, f, 1.3333558146428443e-3f);
    r = fmaf(r, f, 9.6181291076284772e-3f);
    r = fmaf(r, f, 5.5504108664821580e-2f);
    r = fmaf(r, f, 2.4022650695910072e-1f);
    r = fmaf(r, f, 6.9314718055994531e-1f);
    r = fmaf(r, f, 1.0f);
    return __int_as_float(__float_as_int(r) + (n << 23));
}

__device__ __forceinline__ unsigned short bfu(__nv_bfloat16 b) {
    return __bfloat16_as_ushort(b);
}
// pack (lo elem, hi elem) bf16 pair into uint32 (memory order)
__device__ __forceinline__ uint32_t packbf(float a, float b) {
    return (uint32_t)bfu(__float2bfloat16(a)) |
           ((uint32_t)bfu(__float2bfloat16(b)) << 16);
}
__device__ __forceinline__ float2 bf2f(uint32_t w) {
    __nv_bfloat162 b = *reinterpret_cast<__nv_bfloat162*>(&w);
    return make_float2(__bfloat162float(b.x), __bfloat162float(b.y));
}

// ---------------------------------------------------------------------------
// K0: split Wo into bf16 hi/lo
// ---------------------------------------------------------------------------
__global__ __launch_bounds__(256) void wo_split_kernel(const float* __restrict__ Wo)
{
    int i = blockIdx.x * 256 + threadIdx.x;
    if (i < D_ * D_) {
        float v = Wo[i];
        __nv_bfloat16 hb = __float2bfloat16(v);
        g_woh[i] = hb;
        g_wol[i] = __float2bfloat16(v - __bfloat162float(hb));
    }
}

// ---------------------------------------------------------------------------
// K1: QKV projection (fp32 FFMA) -> bf16 hi/lo outputs.
// ---------------------------------------------------------------------------
__global__ __launch_bounds__(256) void qkv_kernel(
    const float* __restrict__ xyz,
    const float* __restrict__ Wq,
    const float* __restrict__ Wk,
    const float* __restrict__ Wv)
{
    __shared__ float xs[64][65];
    __shared__ float Wt[64][68];

    int ptile = blockIdx.x, nh = blockIdx.y;
    int n = nh / H_, h = nh % H_;
    int p0 = ptile * 64;
    int tid = threadIdx.x;

    for (int i = tid; i < 4096; i += 256) {
        int row = i >> 6, dd = i & 63;
        xs[row][dd] = xyz[(n * P_ + p0 + row) * D_ + h * HD_ + dd];
    }

    int tx = tid & 15, ty = tid >> 4;
    int r = ty * 4, c = tx * 4;
    const float* Ws[3] = {Wq, Wk, Wv};

    for (int m = 0; m < 3; ++m) {
        __syncthreads();
        const float* W = Ws[m];
        for (int i = tid; i < 4096; i += 256) {
            int e = i >> 6, dd = i & 63;
            Wt[dd][e] = W[i];
        }
        __syncthreads();

        float acc[4][4] = {};
        #pragma unroll
        for (int dd = 0; dd < 64; ++dd) {
            float a0 = xs[r + 0][dd], a1 = xs[r + 1][dd];
            float a2 = xs[r + 2][dd], a3 = xs[r + 3][dd];
            float4 b = *(const float4*)&Wt[dd][c];
            acc[0][0] += a0 * b.x; acc[0][1] += a0 * b.y; acc[0][2] += a0 * b.z; acc[0][3] += a0 * b.w;
            acc[1][0] += a1 * b.x; acc[1][1] += a1 * b.y; acc[1][2] += a1 * b.z; acc[1][3] += a1 * b.w;
            acc[2][0] += a2 * b.x; acc[2][1] += a2 * b.y; acc[2][2] += a2 * b.z; acc[2][3] += a2 * b.w;
            acc[3][0] += a3 * b.x; acc[3][1] += a3 * b.y; acc[3][2] += a3 * b.z; acc[3][3] += a3 * b.w;
        }

        if (m < 2) {
            float sc = (m == 0) ? SCALE_ : 1.0f;
            __nv_bfloat16* Ah = (m == 0) ? g_qh : g_kh;
            __nv_bfloat16* Al = (m == 0) ? g_ql : g_kl;
            #pragma unroll
            for (int i = 0; i < 4; ++i) {
                long long idx = ((long long)(nh * P_ + p0 + r + i)) * 64 + c;
                float v0 = acc[i][0] * sc, v1 = acc[i][1] * sc;
                float v2 = acc[i][2] * sc, v3 = acc[i][3] * sc;
                __nv_bfloat16 h0 = __float2bfloat16(v0), h1 = __float2bfloat16(v1);
                __nv_bfloat16 h2 = __float2bfloat16(v2), h3 = __float2bfloat16(v3);
                *(ushort4*)&Ah[idx] = make_ushort4(bfu(h0), bfu(h1), bfu(h2), bfu(h3));
                *(ushort4*)&Al[idx] = make_ushort4(
                    bfu(__float2bfloat16(v0 - __bfloat162float(h0))),
                    bfu(__float2bfloat16(v1 - __bfloat162float(h1))),
                    bfu(__float2bfloat16(v2 - __bfloat162float(h2))),
                    bfu(__float2bfloat16(v3 - __bfloat162float(h3))));
            }
        } else {
            __syncthreads();
            #pragma unroll
            for (int i = 0; i < 4; ++i)
                #pragma unroll
                for (int j = 0; j < 4; ++j)
                    xs[c + j][r + i] = acc[i][j];
            __syncthreads();
            for (int i = tid; i < 4096; i += 256) {
                int e = i >> 6, pp = i & 63;
                float v = xs[e][pp];
                __nv_bfloat16 hb = __float2bfloat16(v);
                long long idx = (long long)(nh * 64 + e) * P_ + p0 + pp;
                g_vth[idx] = hb;
                g_vtl[idx] = __float2bfloat16(v - __bfloat162float(hb));
            }
        }
    }
}

// ---------------------------------------------------------------------------
// K2: S = QK^T via mma.sync bf16 hi/lo (3 passes).
//   Epilogue: per-tile row stats -> g_pm/g_ps; u = exp(S - m_tile) split to
//   bf16 hi/lo and streamed to g_uh/g_ul (no fp32 S traffic at all).
// smem (dynamic 73728): operands QH 0 / QL 18432 / KH 36864 / KL 55296
//   (128 x 72 bf16, stride 144B). After MMA reused:
//   UHS 0, ULS 34816 (128 x 136 bf16, stride 272B);
//   Mrow 69632(512B), wmax 70144(1KB), wsum 71168(1KB).
// ---------------------------------------------------------------------------
constexpr int TSB = 144;

__global__ __launch_bounds__(256) void scores_tc()
{
    extern __shared__ char sm[];
    uint32_t sb = smem_u32(sm);
    int tid = threadIdx.x, lane = tid & 31, wid = tid >> 5;
    int kt = blockIdx.x, qt = blockIdx.y, nh = blockIdx.z;
    int q0 = qt * 128, k0 = kt * 128;

    const int QH = 0, QL = 18432, KH = 36864, KL = 55296;
    {
        const __nv_bfloat16* srcs[4] = {
            g_qh + (long long)(nh * P_ + q0) * 64,
            g_ql + (long long)(nh * P_ + q0) * 64,
            g_kh + (long long)(nh * P_ + k0) * 64,
            g_kl + (long long)(nh * P_ + k0) * 64};
        const int offs[4] = {QH, QL, KH, KL};
        #pragma unroll
        for (int t = 0; t < 4; ++t) {
            #pragma unroll
            for (int i = 0; i < 4; ++i) {
                int lin = i * 256 + tid;
                int row = lin >> 3, c8 = lin & 7;
                *(uint4*)(sm + offs[t] + row * TSB + c8 * 16) =
                    *(const uint4*)(srcs[t] + row * 64 + c8 * 8);
            }
        }
    }
    __syncthreads();

    int wm = wid >> 1, wn = wid & 1;
    float acc[2][8][4] = {};
    uint32_t aoff = (uint32_t)(wm * 32 + (lane & 15)) * TSB + ((lane & 16) ? 16u : 0u);
    uint32_t boff = (uint32_t)(wn * 64 + (lane & 7) + ((lane & 16) ? 8 : 0)) * TSB +
                    ((lane & 8) ? 16u : 0u);

    #pragma unroll
    for (int pass = 0; pass < 3; ++pass) {
        uint32_t Ab = sb + (pass == 2 ? QL : QH);
        uint32_t Bb = sb + (pass == 1 ? KL : KH);
        #pragma unroll
        for (int ks = 0; ks < 4; ++ks) {
            uint32_t af[2][4], bf2[4][4];
            ldsm4(af[0], Ab + aoff + ks * 32);
            ldsm4(af[1], Ab + aoff + 16 * TSB + ks * 32);
            #pragma unroll
            for (int np = 0; np < 4; ++np)
                ldsm4(bf2[np], Bb + boff + np * 16 * TSB + ks * 32);
            #pragma unroll
            for (int mi = 0; mi < 2; ++mi)
                #pragma unroll
                for (int ni = 0; ni < 8; ++ni)
                    mma16816(acc[mi][ni], af[mi],
                             bf2[ni >> 1][(ni & 1) * 2], bf2[ni >> 1][(ni & 1) * 2 + 1]);
        }
    }
    __syncthreads();   // operands fully consumed before smem reuse

    float* Mrow = (float*)(sm + 69632);
    float* wmax = (float*)(sm + 70144);
    float* wsum = (float*)(sm + 71168);
    int g = lane >> 2, tg = lane & 3;

    #pragma unroll
    for (int mi = 0; mi < 2; ++mi)
        #pragma unroll
        for (int h = 0; h < 2; ++h) {
            float m = -1e30f;
            #pragma unroll
            for (int ni = 0; ni < 8; ++ni)
                m = fmaxf(m, fmaxf(acc[mi][ni][h * 2], acc[mi][ni][h * 2 + 1]));
            m = fmaxf(m, __shfl_xor_sync(0xFFFFFFFFu, m, 1));
            m = fmaxf(m, __shfl_xor_sync(0xFFFFFFFFu, m, 2));
            if (tg == 0) wmax[(wm * 32 + mi * 16 + h * 8 + g) * 2 + wn] = m;
        }
    __syncthreads();
    if (tid < 128) {
        float M = fmaxf(wmax[tid * 2], wmax[tid * 2 + 1]);
        Mrow[tid] = M;
        g_pm[(nh * 16 + kt) * P_ + q0 + tid] = M;
    }
    __syncthreads();

    // exp + split + stage (uint32 packed bf16 pairs)
    #pragma unroll
    for (int mi = 0; mi < 2; ++mi)
        #pragma unroll
        for (int h = 0; h < 2; ++h) {
            int row = wm * 32 + mi * 16 + h * 8 + g;
            float M = Mrow[row];
            float s = 0.f;
            #pragma unroll
            for (int ni = 0; ni < 8; ++ni) {
                float u0 = fexp(acc[mi][ni][h * 2] - M);
                float u1 = fexp(acc[mi][ni][h * 2 + 1] - M);
                s += u0 + u1;
                int col = wn * 64 + ni * 8 + tg * 2;
                __nv_bfloat16 h0 = __float2bfloat16(u0);
                __nv_bfloat16 h1 = __float2bfloat16(u1);
                uint32_t ph = (uint32_t)bfu(h0) | ((uint32_t)bfu(h1) << 16);
                uint32_t pl = packbf(u0 - __bfloat162float(h0),
                                     u1 - __bfloat162float(h1));
                *(uint32_t*)(sm + 0     + row * 272 + col * 2) = ph;
                *(uint32_t*)(sm + 34816 + row * 272 + col * 2) = pl;
            }
            s += __shfl_xor_sync(0xFFFFFFFFu, s, 1);
            s += __shfl_xor_sync(0xFFFFFFFFu, s, 2);
            if (tg == 0) wsum[row * 2 + wn] = s;
        }
    __syncthreads();
    if (tid < 128)
        g_ps[(nh * 16 + kt) * P_ + q0 + tid] = wsum[tid * 2] + wsum[tid * 2 + 1];

    long long ub = ((long long)nh << 22) + (long long)q0 * 2048 + k0;
    #pragma unroll
    for (int i = 0; i < 8; ++i) {
        int lin = i * 256 + tid;
        int row = lin >> 4, c16 = lin & 15;
        *(uint4*)(g_uh + ub + (long long)row * 2048 + c16 * 8) =
            *(uint4*)(sm + 0 + row * 272 + c16 * 16);
        *(uint4*)(g_ul + ub + (long long)row * 2048 + c16 * 8) =
            *(uint4*)(sm + 34816 + row * 272 + c16 * 16);
    }
}

// ---------------------------------------------------------------------------
// K3: pv. cp.async double-buffered over 16 k-tiles.
//   probs = (uh+ul)*fac -> attn (output).  O accumulated as
//   acc_total += fac * (U_tile @ V_tile) with per-row per-tile factor.
// smem (dynamic 217088): 2 stages of [UH 0 / UL 34816 (128x136 bf16) /
//   VH 69632 / VL 87040 (64x136 bf16)] (stage size 104448); FACS @208896.
// ---------------------------------------------------------------------------
constexpr int PV_STG = 104448;
constexpr int PV_UH = 0, PV_UL = 34816, PV_VH = 69632, PV_VL = 87040;
constexpr int PV_FACS = 208896;

__global__ __launch_bounds__(256) void pv_tc(float* __restrict__ attn)
{
    extern __shared__ char sm[];
    uint32_t sb = smem_u32(sm);
    int tid = threadIdx.x, lane = tid & 31, wid = tid >> 5;
    int qt = blockIdx.x, nh = blockIdx.y;
    int q0 = qt * 128;

    const __nv_bfloat16* vhp = g_vth + (long long)nh * 64 * P_;
    const __nv_bfloat16* vlp = g_vtl + (long long)nh * 64 * P_;
    long long ub = ((long long)nh << 22) + (long long)q0 * 2048;
    float* facs = (float*)(sm + PV_FACS);

    // prefetch tile 0 into stage 0
    {
        uint32_t st = sb;
        #pragma unroll
        for (int i = 0; i < 8; ++i) {
            int lin = i * 256 + tid;
            int row = lin >> 4, c16 = lin & 15;
            cpa16(st + PV_UH + row * 272 + c16 * 16,
                  g_uh + ub + (long long)row * 2048 + c16 * 8);
            cpa16(st + PV_UL + row * 272 + c16 * 16,
                  g_ul + ub + (long long)row * 2048 + c16 * 8);
        }
        #pragma unroll
        for (int i = 0; i < 4; ++i) {
            int lin = i * 256 + tid;
            int row = lin >> 4, c16 = lin & 15;
            cpa16(st + PV_VH + row * 272 + c16 * 16,
                  vhp + (long long)row * P_ + c16 * 8);
            cpa16(st + PV_VL + row * 272 + c16 * 16,
                  vlp + (long long)row * P_ + c16 * 8);
        }
        CP_COMMIT();
    }

    // softmax combine factors (overlaps with prefetch)
    if (tid < 128) {
        float pm[16];
        float M = -1e30f;
        #pragma unroll
        for (int t = 0; t < 16; ++t) {
            pm[t] = g_pm[(nh * 16 + t) * P_ + q0 + tid];
            M = fmaxf(M, pm[t]);
        }
        float L = 0.f, e[16];
        #pragma unroll
        for (int t = 0; t < 16; ++t) {
            e[t] = fexp(pm[t] - M);
            L += g_ps[(nh * 16 + t) * P_ + q0 + tid] * e[t];
        }
        float inv = 1.f / L;
        #pragma unroll
        for (int t = 0; t < 16; ++t) facs[tid * 16 + t] = e[t] * inv;
    }

    float* S = attn + ub;
    float acc[8][4] = {};
    uint32_t aoff = (uint32_t)(wid * 16 + (lane & 15)) * 272 + ((lane & 16) ? 16u : 0u);
    uint32_t boff = (uint32_t)((lane & 7) + ((lane & 16) ? 8 : 0)) * 272 +
                    ((lane & 8) ? 16u : 0u);
    int g = lane >> 2;

    #pragma unroll 1
    for (int kb = 0; kb < 16; ++kb) {
        if (kb + 1 < 16) {   // prefetch next tile
            uint32_t st = sb + ((kb + 1) & 1) * PV_STG;
            int k1 = (kb + 1) * 128;
            #pragma unroll
            for (int i = 0; i < 8; ++i) {
                int lin = i * 256 + tid;
                int row = lin >> 4, c16 = lin & 15;
                cpa16(st + PV_UH + row * 272 + c16 * 16,
                      g_uh + ub + (long long)row * 2048 + k1 + c16 * 8);
                cpa16(st + PV_UL + row * 272 + c16 * 16,
                      g_ul + ub + (long long)row * 2048 + k1 + c16 * 8);
            }
            #pragma unroll
            for (int i = 0; i < 4; ++i) {
                int lin = i * 256 + tid;
                int row = lin >> 4, c16 = lin & 15;
                cpa16(st + PV_VH + row * 272 + c16 * 16,
                      vhp + (long long)row * P_ + k1 + c16 * 8);
                cpa16(st + PV_VL + row * 272 + c16 * 16,
                      vlp + (long long)row * P_ + k1 + c16 * 8);
            }
            CP_COMMIT();
            CP_WAIT1();
        } else {
            CP_WAIT0();
        }
        __syncthreads();

        uint32_t st = sb + (kb & 1) * PV_STG;
        char*    stc = sm + (kb & 1) * PV_STG;

        // MMA: acc_t = U_tile @ V_tile (3 hi/lo passes), then rescale-accum
        float acc_t[8][4] = {};
        #pragma unroll
        for (int pass = 0; pass < 3; ++pass) {
            uint32_t Ab = st + (pass == 2 ? PV_UL : PV_UH);
            uint32_t Bb = st + (pass == 1 ? PV_VL : PV_VH);
            #pragma unroll
            for (int ks = 0; ks < 8; ++ks) {
                uint32_t af[4], bf2[4][4];
                ldsm4(af, Ab + aoff + ks * 32);
                #pragma unroll
                for (int np = 0; np < 4; ++np)
                    ldsm4(bf2[np], Bb + boff + np * 16 * 272 + ks * 32);
                #pragma unroll
                for (int ni = 0; ni < 8; ++ni)
                    mma16816(acc_t[ni], af,
                             bf2[ni >> 1][(ni & 1) * 2], bf2[ni >> 1][(ni & 1) * 2 + 1]);
            }
        }
        float c0 = facs[(wid * 16 + g) * 16 + kb];
        float c1 = facs[(wid * 16 + 8 + g) * 16 + kb];
        #pragma unroll
        for (int ni = 0; ni < 8; ++ni) {
            acc[ni][0] = fmaf(c0, acc_t[ni][0], acc[ni][0]);
            acc[ni][1] = fmaf(c0, acc_t[ni][1], acc[ni][1]);
            acc[ni][2] = fmaf(c1, acc_t[ni][2], acc[ni][2]);
            acc[ni][3] = fmaf(c1, acc_t[ni][3], acc[ni][3]);
        }

        // probs output: p = (uh+ul)*fac, streamed from smem
        int k0 = kb * 128;
        #pragma unroll 4
        for (int i = 0; i < 16; ++i) {
            int lin = i * 256 + tid;
            int row = lin >> 5, c4 = lin & 31;
            uint2 wh = *(uint2*)(stc + PV_UH + row * 272 + c4 * 8);
            uint2 wl = *(uint2*)(stc + PV_UL + row * 272 + c4 * 8);
            float fac = facs[row * 16 + kb];
            float2 h0 = bf2f(wh.x), h1 = bf2f(wh.y);
            float2 l0 = bf2f(wl.x), l1 = bf2f(wl.y);
            *(float4*)&S[(long long)row * 2048 + k0 + c4 * 4] =
                make_float4((h0.x + l0.x) * fac, (h0.y + l0.y) * fac,
                            (h1.x + l1.x) * fac, (h1.y + l1.y) * fac);
        }
        __syncthreads();
    }

    // Epilogue: stage O fp32, then bf16 hi/lo to g_oh/g_ol [n][p][512]
    int tg = lane & 3;
    float* Ost = (float*)sm;  // stride 68 floats (reuse stage 0)
    #pragma unroll
    for (int h = 0; h < 2; ++h) {
        int row = wid * 16 + h * 8 + g;
        #pragma unroll
        for (int ni = 0; ni < 8; ++ni)
            *(float2*)&Ost[row * 68 + ni * 8 + tg * 2] =
                make_float2(acc[ni][h * 2], acc[ni][h * 2 + 1]);
    }
    __syncthreads();
    int n = nh >> 3, h = nh & 7;
    #pragma unroll
    for (int i = 0; i < 4; ++i) {
        int lin = i * 256 + tid;
        int row = lin >> 3, c8 = lin & 7;
        long long dst = ((long long)(n * P_ + q0 + row)) * 512 + h * 64 + c8 * 8;
        ushort4 uh4a, uh4b, ul4a, ul4b;
        const float* src = &Ost[row * 68 + c8 * 8];
        float v0 = src[0], v1 = src[1], v2 = src[2], v3 = src[3];
        float v4 = src[4], v5 = src[5], v6 = src[6], v7 = src[7];
        __nv_bfloat16 b0 = __float2bfloat16(v0), b1 = __float2bfloat16(v1);
        __nv_bfloat16 b2 = __float2bfloat16(v2), b3 = __float2bfloat16(v3);
        __nv_bfloat16 b4 = __float2bfloat16(v4), b5 = __float2bfloat16(v5);
        __nv_bfloat16 b6 = __float2bfloat16(v6), b7 = __float2bfloat16(v7);
        uh4a = make_ushort4(bfu(b0), bfu(b1), bfu(b2), bfu(b3));
        uh4b = make_ushort4(bfu(b4), bfu(b5), bfu(b6), bfu(b7));
        ul4a = make_ushort4(bfu(__float2bfloat16(v0 - __bfloat162float(b0))),
                            bfu(__float2bfloat16(v1 - __bfloat162float(b1))),
                            bfu(__float2bfloat16(v2 - __bfloat162float(b2))),
                            bfu(__float2bfloat16(v3 - __bfloat162float(b3))));
        ul4b = make_ushort4(bfu(__float2bfloat16(v4 - __bfloat162float(b4))),
                            bfu(__float2bfloat16(v5 - __bfloat162float(b5))),
                            bfu(__float2bfloat16(v6 - __bfloat162float(b6))),
                            bfu(__float2bfloat16(v7 - __bfloat162float(b7))));
        *(ushort4*)&g_oh[dst]     = uh4a;
        *(ushort4*)&g_oh[dst + 4] = uh4b;
        *(ushort4*)&g_ol[dst]     = ul4a;
        *(ushort4*)&g_ol[dst + 4] = ul4b;
    }
}

// ---------------------------------------------------------------------------
// K4: out = O_flat @ Wo^T + bo via mma.sync bf16 hi/lo.
// Tile 128 rows x 128 cols, k-chunks of 64 (8 chunks).
// smem (dynamic 73728): AH 0 / AL 18432 / BH 36864 / BL 55296 (stride 144B).
// ---------------------------------------------------------------------------
__global__ __launch_bounds__(256) void outproj_tc(
    const float* __restrict__ bo,
    float* __restrict__ out)
{
    extern __shared__ char sm[];
    uint32_t sb = smem_u32(sm);
    int tid = threadIdx.x, lane = tid & 31, wid = tid >> 5;
    int ct = blockIdx.x, rt = blockIdx.y;
    int r0 = rt * 128, c0 = ct * 128;

    const int AH = 0, AL = 18432, BH = 36864, BL = 55296;
    int wm = wid >> 1, wn = wid & 1;
    float acc[2][8][4] = {};
    uint32_t aoff = (uint32_t)(wm * 32 + (lane & 15)) * TSB + ((lane & 16) ? 16u : 0u);
    uint32_t boff = (uint32_t)(wn * 64 + (lane & 7) + ((lane & 16) ? 8 : 0)) * TSB +
                    ((lane & 8) ? 16u : 0u);

    #pragma unroll 1
    for (int kb = 0; kb < 8; ++kb) {
        int k0 = kb * 64;
        #pragma unroll
        for (int i = 0; i < 4; ++i) {
            int lin = i * 256 + tid;
            int row = lin >> 3, c8 = lin & 7;
            long long asrc = (long long)(r0 + row) * 512 + k0 + c8 * 8;
            long long bsrc = (long long)(c0 + row) * 512 + k0 + c8 * 8;
            *(uint4*)(sm + AH + row * TSB + c8 * 16) = *(const uint4*)(g_oh + asrc);
            *(uint4*)(sm + AL + row * TSB + c8 * 16) = *(const uint4*)(g_ol + asrc);
            *(uint4*)(sm + BH + row * TSB + c8 * 16) = *(const uint4*)(g_woh + bsrc);
            *(uint4*)(sm + BL + row * TSB + c8 * 16) = *(const uint4*)(g_wol + bsrc);
        }
        __syncthreads();

        #pragma unroll
        for (int pass = 0; pass < 3; ++pass) {
            uint32_t Ab = sb + (pass == 2 ? AL : AH);
            uint32_t Bb = sb + (pass == 1 ? BL : BH);
            #pragma unroll
            for (int ks = 0; ks < 4; ++ks) {
                uint32_t af[2][4], bf2[4][4];
                ldsm4(af[0], Ab + aoff + ks * 32);
                ldsm4(af[1], Ab + aoff + 16 * TSB + ks * 32);
                #pragma unroll
                for (int np = 0; np < 4; ++np)
                    ldsm4(bf2[np], Bb + boff + np * 16 * TSB + ks * 32);
                #pragma unroll
                for (int mi = 0; mi < 2; ++mi)
                    #pragma unroll
                    for (int ni = 0; ni < 8; ++ni)
                        mma16816(acc[mi][ni], af[mi],
                                 bf2[ni >> 1][(ni & 1) * 2], bf2[ni >> 1][(ni & 1) * 2 + 1]);
            }
        }
        __syncthreads();
    }

    int g = lane >> 2, tg = lane & 3;
    #pragma unroll
    for (int ni = 0; ni < 8; ++ni) {
        int col = wn * 64 + ni * 8 + tg * 2;
        float2 bb = *(const float2*)&bo[c0 + col];
        #pragma unroll
        for (int mi = 0; mi < 2; ++mi)
            #pragma unroll
            for (int h = 0; h < 2; ++h) {
                int row = wm * 32 + mi * 16 + h * 8 + g;
                *(float2*)&out[(long long)(r0 + row) * 512 + c0 + col] =
                    make_float2(acc[mi][ni][h * 2] + bb.x,
                                acc[mi][ni][h * 2 + 1] + bb.y);
            }
    }
}

// ---------------------------------------------------------------------------
extern "C" void kernel_launch(void* const* d_in, const int* in_sizes, int n_in,
                              void* d_out, int out_size)
{
    const float* xyz = (const float*)d_in[0];
    const float* Wq  = (const float*)d_in[1];
    const float* Wk  = (const float*)d_in[2];
    const float* Wv  = (const float*)d_in[3];
    const float* Wo  = (const float*)d_in[4];
    const float* bo  = (const float*)d_in[5];
    float* out = (float*)d_out;

    float* attn;
    if ((long long)out_size >= NPD_ + NHPP_) {
        attn = out + NPD_;
    } else {
        void* p = nullptr;
        cudaGetSymbolAddress(&p, g_attn);
        attn = (float*)p;
    }

    cudaFuncSetAttribute(scores_tc,  cudaFuncAttributeMaxDynamicSharedMemorySize, 73728);
    cudaFuncSetAttribute(pv_tc,      cudaFuncAttributeMaxDynamicSharedMemorySize, 217088);
    cudaFuncSetAttribute(outproj_tc, cudaFuncAttributeMaxDynamicSharedMemorySize, 73728);

    wo_split_kernel<<<(D_ * D_ + 255) / 256, 256>>>(Wo);
    qkv_kernel<<<dim3(P_ / 64, NH_), 256>>>(xyz, Wq, Wk, Wv);
    scores_tc<<<dim3(16, 16, NH_), 256, 73728>>>();
    pv_tc<<<dim3(16, NH_), 256, 217088>>>(attn);
    outproj_tc<<<dim3(4, 64), 256, 73728>>>(bo, out);
}